// round 14
// baseline (speedup 1.0000x reference)
#include <cuda_runtime.h>

#define NC    21
#define HW    (512 * 512)
#define NB    16
#define BHW   (NB * HW)
#define NBINS (NC * NC)
#define GRID  2048

// Zero at module load; the electing last block resets both after use so every
// launch (correctness run, capture, every graph replay) starts clean.
__device__ unsigned int g_conf[NBINS];
__device__ unsigned int g_done;

// Main loop identical to the fastest-measured R3/R11 hist kernel. The
// (256, 6) bound caps regs at 42 — the hist loop's natural allocation — so
// the loop codegen/MLP is preserved while the once-only epilogue spills.
__global__ void __launch_bounds__(256, 6)
fused_kernel(const float* __restrict__ logits, const int* __restrict__ target,
             float* __restrict__ out) {
    __shared__ unsigned int s_conf[NBINS];
    __shared__ bool s_last;
    for (int i = threadIdx.x; i < NBINS; i += 256) s_conf[i] = 0u;
    __syncthreads();

    const int nquads = BHW / 4;  // 1,048,576 quads of 4 pixels
    for (int q = blockIdx.x * 256 + threadIdx.x; q < nquads;
         q += gridDim.x * 256) {
        int p = q << 2;                 // pixel index (multiple of 4, stays in same b)
        int b = p / HW;
        int s = p - b * HW;
        const float4* base =
            (const float4*)(logits + (size_t)b * NC * HW + s);

        float4 v = __ldg(base);
        float m0 = v.x, m1 = v.y, m2 = v.z, m3 = v.w;
        int a0 = 0, a1 = 0, a2 = 0, a3 = 0;
        #pragma unroll
        for (int c = 1; c < NC; c++) {
            float4 u = __ldg(base + (size_t)c * (HW / 4));
            if (u.x > m0) { m0 = u.x; a0 = c; }
            if (u.y > m1) { m1 = u.y; a1 = c; }
            if (u.z > m2) { m2 = u.z; a2 = c; }
            if (u.w > m3) { m3 = u.w; a3 = c; }
        }

        int4 t = *(const int4*)(target + p);   // 16B-aligned: p % 4 == 0
        atomicAdd(&s_conf[t.x * NC + a0], 1u);
        atomicAdd(&s_conf[t.y * NC + a1], 1u);
        atomicAdd(&s_conf[t.z * NC + a2], 1u);
        atomicAdd(&s_conf[t.w * NC + a3], 1u);
    }

    __syncthreads();
    for (int i = threadIdx.x; i < NBINS; i += 256) {
        unsigned int v = s_conf[i];
        if (v) atomicAdd(&g_conf[i], v);
    }

    // Publish this block's flush, then elect the last-finishing block.
    __threadfence();
    __syncthreads();
    if (threadIdx.x == 0) {
        unsigned int n = atomicAdd(&g_done, 1u);
        s_last = (n == GRID - 1);
    }
    __syncthreads();
    if (!s_last) return;

    // ---- last block only: loss epilogue + state reset (register-lean) ----
    int i = threadIdx.x;
    for (int k = i; k < NBINS; k += 256)
        s_conf[k] = g_conf[k];   // all flushes visible (fence + atomic order)
    __syncthreads();
    for (int k = i; k < NBINS; k += 256) g_conf[k] = 0u;  // reset for next run
    if (i == 0) g_done = 0u;

    float acc = 0.0f;
    if (i < NC) {
        float tp = (float)s_conf[i * NC + i];
        float rowsum = 0.0f, colsum = 0.0f;
        #pragma unroll 1
        for (int j = 0; j < NC; j++) rowsum += (float)s_conf[i * NC + j];
        #pragma unroll 1
        for (int j = 0; j < NC; j++) colsum += (float)s_conf[j * NC + i];
        float fp = rowsum - tp;
        float fn = colsum - tp;
        float tn = (float)BHW - tp - fp - fn;
        float sens = (tp + 1.0f) / (tp + fn + 1.0f);
        float spec = (tn + 1.0f) / (tn + fp + 1.0f);
        acc = 0.5f * sens + 0.5f * spec;
    }
    if (i < 32) {   // classes 0..20 all live in warp 0
        #pragma unroll
        for (int off = 16; off > 0; off >>= 1)
            acc += __shfl_down_sync(0xffffffffu, acc, off);
        if (i == 0) out[0] = 1.0f - acc / (float)NC;
    }
}

extern "C" void kernel_launch(void* const* d_in, const int* in_sizes, int n_in,
                              void* d_out, int out_size) {
    const float* logits = (const float*)d_in[0];
    const int* target   = (const int*)d_in[1];
    float* out = (float*)d_out;

    fused_kernel<<<GRID, 256>>>(logits, target, out);
}

// round 15
// speedup vs baseline: 1.1212x; 1.1212x over previous
#include <cuda_runtime.h>

#define NC    21
#define HW    (512 * 512)
#define NB    16
#define BHW   (NB * HW)
#define NBINS (NC * NC)
#define GRID  2048

// Zero at module load; the electing last block resets both after use so every
// launch (correctness run, capture, every graph replay) starts clean.
__device__ unsigned int g_conf[NBINS];
__device__ unsigned int g_done;

// Main loop identical to the fastest-measured R3/R11 hist kernel.
// Publication uses a gpu-scoped acq_rel atomic (NO __threadfence -> no
// CCTL.IVALL L1 flush, which is the suspected fused-kernel slowdown).
__global__ void __launch_bounds__(256)
fused_kernel(const float* __restrict__ logits, const int* __restrict__ target,
             float* __restrict__ out) {
    __shared__ unsigned int s_conf[NBINS];
    __shared__ bool s_last;
    for (int i = threadIdx.x; i < NBINS; i += 256) s_conf[i] = 0u;
    __syncthreads();

    const int nquads = BHW / 4;  // 1,048,576 quads of 4 pixels
    for (int q = blockIdx.x * 256 + threadIdx.x; q < nquads;
         q += gridDim.x * 256) {
        int p = q << 2;                 // pixel index (multiple of 4, stays in same b)
        int b = p / HW;
        int s = p - b * HW;
        const float4* base =
            (const float4*)(logits + (size_t)b * NC * HW + s);

        float4 v = __ldg(base);
        float m0 = v.x, m1 = v.y, m2 = v.z, m3 = v.w;
        int a0 = 0, a1 = 0, a2 = 0, a3 = 0;
        #pragma unroll
        for (int c = 1; c < NC; c++) {
            float4 u = __ldg(base + (size_t)c * (HW / 4));
            if (u.x > m0) { m0 = u.x; a0 = c; }
            if (u.y > m1) { m1 = u.y; a1 = c; }
            if (u.z > m2) { m2 = u.z; a2 = c; }
            if (u.w > m3) { m3 = u.w; a3 = c; }
        }

        int4 t = *(const int4*)(target + p);   // 16B-aligned: p % 4 == 0
        atomicAdd(&s_conf[t.x * NC + a0], 1u);
        atomicAdd(&s_conf[t.y * NC + a1], 1u);
        atomicAdd(&s_conf[t.z * NC + a2], 1u);
        atomicAdd(&s_conf[t.w * NC + a3], 1u);
    }

    __syncthreads();
    for (int i = threadIdx.x; i < NBINS; i += 256) {
        unsigned int v = s_conf[i];
        if (v) atomicAdd(&g_conf[i], v);
    }
    __syncthreads();   // all flush atomics of this block issued

    // Release-publish this block's flush and elect the last block, without
    // any L1-invalidating fence. acq_rel: release pairs with the last
    // block's acquire on the same location.
    if (threadIdx.x == 0) {
        unsigned int n;
        asm volatile("atom.acq_rel.gpu.global.add.u32 %0, [%1], %2;"
                     : "=r"(n) : "l"(&g_done), "r"(1u) : "memory");
        s_last = (n == GRID - 1);
    }
    __syncthreads();
    if (!s_last) return;

    // ---- last block only: loss epilogue + state reset ----
    int i = threadIdx.x;
    for (int k = i; k < NBINS; k += 256)
        s_conf[k] = __ldcg(&g_conf[k]);   // L2-direct read (skip L1)
    __syncthreads();
    for (int k = i; k < NBINS; k += 256) g_conf[k] = 0u;  // reset for next run
    if (i == 0) g_done = 0u;

    float acc = 0.0f;
    if (i < NC) {
        float tp = (float)s_conf[i * NC + i];
        float rowsum = 0.0f, colsum = 0.0f;
        #pragma unroll 1
        for (int j = 0; j < NC; j++) rowsum += (float)s_conf[i * NC + j];
        #pragma unroll 1
        for (int j = 0; j < NC; j++) colsum += (float)s_conf[j * NC + i];
        float fp = rowsum - tp;
        float fn = colsum - tp;
        float tn = (float)BHW - tp - fp - fn;
        float sens = (tp + 1.0f) / (tp + fn + 1.0f);
        float spec = (tn + 1.0f) / (tn + fp + 1.0f);
        acc = 0.5f * sens + 0.5f * spec;
    }
    if (i < 32) {   // classes 0..20 all live in warp 0
        #pragma unroll
        for (int off = 16; off > 0; off >>= 1)
            acc += __shfl_down_sync(0xffffffffu, acc, off);
        if (i == 0) out[0] = 1.0f - acc / (float)NC;
    }
}

extern "C" void kernel_launch(void* const* d_in, const int* in_sizes, int n_in,
                              void* d_out, int out_size) {
    const float* logits = (const float*)d_in[0];
    const int* target   = (const int*)d_in[1];
    float* out = (float*)d_out;

    fused_kernel<<<GRID, 256>>>(logits, target, out);
}

// round 16
// speedup vs baseline: 1.1923x; 1.0634x over previous
#include <cuda_runtime.h>

#define NC    21
#define HW    (512 * 512)
#define NB    16
#define BHW   (NB * HW)
#define NBINS (NC * NC)
#define QPI   (HW / 4)          /* float4 quads per image plane = 65536 */
#define HALFQ (1 << 19)         /* half of the 2^20 total quads */

// Confusion-matrix scratch. Zero at module load (BSS); loss_kernel re-zeroes it
// after consuming it, so every launch (incl. graph replays) starts clean.
__device__ unsigned int g_conf[NBINS];

__global__ void __launch_bounds__(256)
hist_kernel(const float* __restrict__ logits, const int* __restrict__ target) {
    __shared__ unsigned int s_conf[NBINS];
    for (int i = threadIdx.x; i < NBINS; i += 256) s_conf[i] = 0u;
    __syncthreads();

    // Thread g handles quads g and g+HALFQ: adjacent lanes -> adjacent quads
    // in BOTH streams (perfect 128B coalescing), two independent chains (2x MLP).
    int g  = blockIdx.x * 256 + threadIdx.x;     // 0 .. 2^19-1
    int q1 = g;
    int q2 = g + HALFQ;

    int b1 = q1 >> 16;                      // q / QPI
    int s1 = (q1 - (b1 << 16)) << 2;
    int b2 = q2 >> 16;
    int s2 = (q2 - (b2 << 16)) << 2;
    const float4* base1 = (const float4*)(logits + (size_t)b1 * NC * HW + s1);
    const float4* base2 = (const float4*)(logits + (size_t)b2 * NC * HW + s2);

    float4 v1 = __ldg(base1);
    float4 v2 = __ldg(base2);
    float m0 = v1.x, m1 = v1.y, m2 = v1.z, m3 = v1.w;
    float n0 = v2.x, n1 = v2.y, n2 = v2.z, n3 = v2.w;
    int a0 = 0, a1 = 0, a2 = 0, a3 = 0;
    int c0 = 0, c1 = 0, c2 = 0, c3 = 0;
    #pragma unroll
    for (int c = 1; c < NC; c++) {
        float4 u1 = __ldg(base1 + (size_t)c * QPI);
        float4 u2 = __ldg(base2 + (size_t)c * QPI);
        if (u1.x > m0) { m0 = u1.x; a0 = c; }
        if (u1.y > m1) { m1 = u1.y; a1 = c; }
        if (u1.z > m2) { m2 = u1.z; a2 = c; }
        if (u1.w > m3) { m3 = u1.w; a3 = c; }
        if (u2.x > n0) { n0 = u2.x; c0 = c; }
        if (u2.y > n1) { n1 = u2.y; c1 = c; }
        if (u2.z > n2) { n2 = u2.z; c2 = c; }
        if (u2.w > n3) { n3 = u2.w; c3 = c; }
    }

    int4 t1 = __ldg((const int4*)(target + (q1 << 2)));   // 16B-aligned
    int4 t2 = __ldg((const int4*)(target + (q2 << 2)));
    atomicAdd(&s_conf[t1.x * NC + a0], 1u);
    atomicAdd(&s_conf[t1.y * NC + a1], 1u);
    atomicAdd(&s_conf[t1.z * NC + a2], 1u);
    atomicAdd(&s_conf[t1.w * NC + a3], 1u);
    atomicAdd(&s_conf[t2.x * NC + c0], 1u);
    atomicAdd(&s_conf[t2.y * NC + c1], 1u);
    atomicAdd(&s_conf[t2.z * NC + c2], 1u);
    atomicAdd(&s_conf[t2.w * NC + c3], 1u);

    __syncthreads();
    for (int i = threadIdx.x; i < NBINS; i += 256) {
        unsigned int v = s_conf[i];
        if (v) atomicAdd(&g_conf[i], v);
    }
}

// ---- loss_kernel: consumes g_conf, writes scalar, resets state ----
__global__ void __launch_bounds__(512)
loss_kernel(float* __restrict__ out) {
    __shared__ unsigned int s_conf[NBINS];
    int i = threadIdx.x;

    // Snapshot the confusion matrix, then reset it for the next launch/replay.
    if (i < NBINS) s_conf[i] = g_conf[i];
    __syncthreads();
    if (i < NBINS) g_conf[i] = 0u;

    float acc = 0.0f;
    if (i < NC) {
        float tp = (float)s_conf[i * NC + i];
        float rowsum = 0.0f, colsum = 0.0f;
        #pragma unroll
        for (int j = 0; j < NC; j++) {
            rowsum += (float)s_conf[i * NC + j];
            colsum += (float)s_conf[j * NC + i];
        }
        float fp = rowsum - tp;
        float fn = colsum - tp;
        float tn = (float)BHW - tp - fp - fn;
        float sens = (tp + 1.0f) / (tp + fn + 1.0f);
        float spec = (tn + 1.0f) / (tn + fp + 1.0f);
        acc = 0.5f * sens + 0.5f * spec;
    }
    if (i < 32) {   // classes 0..20 all live in warp 0
        #pragma unroll
        for (int off = 16; off > 0; off >>= 1)
            acc += __shfl_down_sync(0xffffffffu, acc, off);
        if (i == 0) out[0] = 1.0f - acc / (float)NC;
    }
}

extern "C" void kernel_launch(void* const* d_in, const int* in_sizes, int n_in,
                              void* d_out, int out_size) {
    const float* logits = (const float*)d_in[0];
    const int* target   = (const int*)d_in[1];
    float* out = (float*)d_out;

    hist_kernel<<<2048, 256>>>(logits, target);
    loss_kernel<<<1, 512>>>(out);
}